// round 16
// baseline (speedup 1.0000x reference)
#include <cuda_runtime.h>
#include <math.h>

#define B   64
#define T   1000
#define RNN 1024
#define EMB 512
#define ATT 128
#define LOC 32
#define KS  31
#define ECH 8
#define ETILE 125
#define TCH 25
#define CTILE 40

__device__ float g_pq[B * ATT];
__device__ float g_energy[B * T];
__device__ float2 g_ms[B * ECH];
__device__ float g_partial[B * TCH * EMB];
__device__ int   g_cnt[B];

__device__ __forceinline__ float fast_tanh(float x) {
    float y;
    asm("tanh.approx.f32 %0, %1;" : "=f"(y) : "f"(x));
    return y;
}
__device__ __forceinline__ unsigned long long fma2(unsigned long long a,
                                                   unsigned long long b,
                                                   unsigned long long c) {
    unsigned long long d;
    asm("fma.rn.f32x2 %0, %1, %2, %3;" : "=l"(d) : "l"(a), "l"(b), "l"(c));
    return d;
}
__device__ __forceinline__ unsigned long long pack2(float lo, float hi) {
    unsigned long long r;
    asm("mov.b64 %0, {%1, %2};" : "=l"(r) : "f"(lo), "f"(hi));
    return r;
}
__device__ __forceinline__ float sum2(unsigned long long p) {
    float lo, hi;
    asm("mov.b64 {%0, %1}, %2;" : "=f"(lo), "=f"(hi) : "l"(p));
    return lo + hi;
}

// ---------------------------------------------------------------------------
// Kernel 1: pq[b][a] = h[b]·Wq[a].  grid(B), block(1024)
// ---------------------------------------------------------------------------
__global__ void k_pq(const float4* __restrict__ h4, const float4* __restrict__ Wq4) {
    int b = blockIdx.x, tid = threadIdx.x;
    int lane = tid & 31, warp = tid >> 5;
    __shared__ float4 sh[RNN / 4];
    if (tid < RNN / 4) sh[tid] = h4[b * (RNN / 4) + tid];
    __syncthreads();
#pragma unroll
    for (int aa = 0; aa < 4; aa++) {
        int a = warp + aa * 32;
        const float4* w = Wq4 + (size_t)a * (RNN / 4);
        float acc = 0.f;
#pragma unroll
        for (int k = 0; k < 8; k++) {
            float4 wv = w[lane + 32 * k];
            float4 hv = sh[lane + 32 * k];
            acc += wv.x * hv.x + wv.y * hv.y + wv.z * hv.z + wv.w * hv.w;
        }
#pragma unroll
        for (int o = 16; o; o >>= 1) acc += __shfl_down_sync(0xffffffffu, acc, o);
        if (lane == 0) g_pq[b * ATT + a] = acc;
    }
}

// ---------------------------------------------------------------------------
// Kernel 2 (TRANSPOSED): thread owns t; a-reduction in registers, no shuffles.
// grid(ECH=8, B), block(128).
// ---------------------------------------------------------------------------
__global__ void __launch_bounds__(128) k_energy(
        const float* __restrict__ pm, const float* __restrict__ aw,
        const float* __restrict__ cw, const float* __restrict__ Wl,
        const float* __restrict__ v,  const unsigned char* __restrict__ mask) {
    int b = blockIdx.y;
    int t0 = blockIdx.x * ETILE;
    int tid = threadIdx.x;
    int lane = tid & 31, warp = tid >> 5;   // 4 warps

    __shared__ __align__(16) unsigned long long s_aw2[ETILE + 32];
    __shared__ __align__(16) unsigned long long s_cw2[LOC * 33];
    __shared__ float s_loc[ETILE * 33];          // pad 33: conflict-free row reads
    __shared__ float s_pm[32 * 129];             // [a'][t], pad 129
    __shared__ float s_pq[ATT], s_v[ATT];
    __shared__ float s_w4[4];

    for (int j = tid; j < ETILE + 30; j += 128) {
        int t = t0 - 15 + j;
        float c0 = 0.f, c1 = 0.f;
        if (t >= 0 && t < T) {
            c0 = aw[(size_t)b * 2 * T + t];
            c1 = aw[(size_t)(b * 2 + 1) * T + t];
        }
        s_aw2[j] = pack2(c0, c1);
    }
    for (int j = tid; j < LOC * KS; j += 128) {
        int c = j / KS, k = j - c * KS;
        s_cw2[c * 33 + k] = pack2(cw[c * 62 + k], cw[c * 62 + 31 + k]);
    }
    if (tid < ATT) { s_pq[tid] = g_pq[b * ATT + tid]; s_v[tid] = v[tid]; }
    __syncthreads();

    // conv: 2 passes of 16 outputs, t = warp + 4*j  (pass2 guarded, t < 125)
    {
        int c = lane, wtt = warp;
        {
            unsigned long long acc2[16];
#pragma unroll
            for (int j = 0; j < 16; j++) acc2[j] = 0ull;
            for (int k = 0; k < KS; k++) {
                unsigned long long cwk = s_cw2[c * 33 + k];
#pragma unroll
                for (int j = 0; j < 16; j++)
                    acc2[j] = fma2(s_aw2[wtt + 4 * j + k], cwk, acc2[j]);
            }
#pragma unroll
            for (int j = 0; j < 16; j++)
                s_loc[(wtt + 4 * j) * 33 + c] = sum2(acc2[j]);
        }
        {
            unsigned long long acc2[16];
#pragma unroll
            for (int j = 0; j < 16; j++) acc2[j] = 0ull;
            for (int k = 0; k < KS; k++) {
                unsigned long long cwk = s_cw2[c * 33 + k];
#pragma unroll
                for (int j = 0; j < 16; j++)
                    if (wtt + 4 * (16 + j) < ETILE)
                        acc2[j] = fma2(s_aw2[wtt + 4 * (16 + j) + k], cwk, acc2[j]);
            }
#pragma unroll
            for (int j = 0; j < 16; j++)
                if (wtt + 4 * (16 + j) < ETILE)
                    s_loc[(wtt + 4 * (16 + j)) * 33 + c] = sum2(acc2[j]);
        }
    }
    __syncthreads();

    // thread's loc row -> registers (conflict-free: bank = (t + c) % 32)
    unsigned long long lc[LOC / 2];
    if (tid < ETILE) {
#pragma unroll
        for (int q = 0; q < LOC / 2; q++)
            lc[q] = pack2(s_loc[tid * 33 + 2 * q], s_loc[tid * 33 + 2 * q + 1]);
    } else {
#pragma unroll
        for (int q = 0; q < LOC / 2; q++) lc[q] = 0ull;
    }

    float acc0 = 0.f, acc1 = 0.f, acc2_ = 0.f, acc3 = 0.f;
    const float* pm_blk = pm + ((size_t)b * T + t0) * ATT;

    for (int chunk = 0; chunk < 4; chunk++) {
        __syncthreads();   // previous s_pm fully consumed
        // stage pm[t][32 a's] transposed: s_pm[a'][t], conflict-free
        for (int i = tid; i < ETILE * 32; i += 128) {
            int t = i >> 5, ap = i & 31;
            s_pm[ap * 129 + t] = pm_blk[(size_t)t * ATT + chunk * 32 + ap];
        }
        __syncthreads();

        if (tid < ETILE) {
#pragma unroll
            for (int ap = 0; ap < 32; ap++) {
                int a = chunk * 32 + ap;
                const ulonglong2* wlp = (const ulonglong2*)(Wl + (size_t)a * LOC);
                unsigned long long A0 = 0ull, A1 = 0ull;
#pragma unroll
                for (int q = 0; q < LOC / 4; q++) {
                    ulonglong2 w = __ldg(&wlp[q]);
                    A0 = fma2(lc[2 * q], w.x, A0);
                    A1 = fma2(lc[2 * q + 1], w.y, A1);
                }
                float x = s_pq[a] + s_pm[ap * 129 + tid] + sum2(A0) + sum2(A1);
                float term = s_v[a] * fast_tanh(x);
                if ((ap & 3) == 0) acc0 += term;
                else if ((ap & 3) == 1) acc1 += term;
                else if ((ap & 3) == 2) acc2_ += term;
                else acc3 += term;
            }
        }
    }

    float e_t = -INFINITY;
    if (tid < ETILE) {
        e_t = (acc0 + acc1) + (acc2_ + acc3);
        int t = t0 + tid;
        if (mask[b * T + t]) e_t = -INFINITY;
        g_energy[b * T + t] = e_t;
    }

    // block softmax partials
    float m = e_t;
#pragma unroll
    for (int o = 16; o; o >>= 1) m = fmaxf(m, __shfl_xor_sync(0xffffffffu, m, o));
    if (lane == 0) s_w4[warp] = m;
    __syncthreads();
    m = fmaxf(fmaxf(s_w4[0], s_w4[1]), fmaxf(s_w4[2], s_w4[3]));
    float s = (tid < ETILE && m > -INFINITY) ? __expf(e_t - m) : 0.f;
#pragma unroll
    for (int o = 16; o; o >>= 1) s += __shfl_xor_sync(0xffffffffu, s, o);
    __syncthreads();
    if (lane == 0) s_w4[warp] = s;
    __syncthreads();
    if (tid == 0) {
        float2 r; r.x = m; r.y = s_w4[0] + s_w4[1] + s_w4[2] + s_w4[3];
        g_ms[b * ECH + blockIdx.x] = r;
    }
}

// ---------------------------------------------------------------------------
// Kernel 3: softmax combine + weights + context partials + fused reduce
// grid(TCH, B), block(128)
// ---------------------------------------------------------------------------
__global__ void __launch_bounds__(128) k_ctx(const float4* __restrict__ mem,
                                             float* __restrict__ out_w,
                                             float* __restrict__ out_ctx) {
    int b = blockIdx.y, ch = blockIdx.x, tid = threadIdx.x;
    int t0 = ch * CTILE;
    __shared__ float sw[CTILE];
    __shared__ float2 sms[ECH];
    __shared__ float s_m, s_inv;
    __shared__ int s_last;

    if (tid < ECH) sms[tid] = g_ms[b * ECH + tid];
    __syncthreads();
    if (tid == 0) {
        float m = -INFINITY;
#pragma unroll
        for (int j = 0; j < ECH; j++) m = fmaxf(m, sms[j].x);
        float S = 0.f;
#pragma unroll
        for (int j = 0; j < ECH; j++)
            if (sms[j].x > -INFINITY) S += sms[j].y * __expf(sms[j].x - m);
        s_m = m; s_inv = 1.f / S;
    }
    __syncthreads();
    if (tid < CTILE) {
        float e = g_energy[b * T + t0 + tid];
        float wv = __expf(e - s_m) * s_inv;
        sw[tid] = wv;
        out_w[b * T + t0 + tid] = wv;
    }
    __syncthreads();

    const float4* mp = mem + ((size_t)b * T + t0) * (EMB / 4) + tid;
    float ax = 0.f, ay = 0.f, az = 0.f, aww = 0.f;
#pragma unroll 20
    for (int tt = 0; tt < CTILE; tt++) {
        float4 m = __ldcs(mp + (size_t)tt * (EMB / 4));
        float wv = sw[tt];
        ax += wv * m.x; ay += wv * m.y; az += wv * m.z; aww += wv * m.w;
    }
    float4 r; r.x = ax; r.y = ay; r.z = az; r.w = aww;
    ((float4*)g_partial)[(b * TCH + ch) * (EMB / 4) + tid] = r;

    __threadfence();
    if (tid == 0) {
        int cprev = atomicAdd(&g_cnt[b], 1);
        s_last = (cprev == TCH - 1);
    }
    __syncthreads();
    if (s_last) {
        __threadfence();
        const float4* pp = (const float4*)g_partial + (size_t)b * TCH * (EMB / 4) + tid;
        float4 acc = pp[0];
#pragma unroll
        for (int chh = 1; chh < TCH; chh++) {
            float4 p = pp[(size_t)chh * (EMB / 4)];
            acc.x += p.x; acc.y += p.y; acc.z += p.z; acc.w += p.w;
        }
        ((float4*)out_ctx)[b * (EMB / 4) + tid] = acc;
        if (tid == 0) g_cnt[b] = 0;
    }
}

// ---------------------------------------------------------------------------
extern "C" void kernel_launch(void* const* d_in, const int* in_sizes, int n_in,
                              void* d_out, int out_size) {
    const float* h    = (const float*)d_in[0];
    const float* mem  = (const float*)d_in[1];
    const float* pm   = (const float*)d_in[2];
    const float* aw   = (const float*)d_in[3];
    const unsigned char* mask = (const unsigned char*)d_in[4];
    const float* Wq   = (const float*)d_in[5];
    const float* cw   = (const float*)d_in[6];
    const float* Wl   = (const float*)d_in[7];
    const float* v    = (const float*)d_in[8];

    float* out     = (float*)d_out;
    float* out_ctx = out;
    float* out_w   = out + B * EMB;

    k_pq<<<B, 1024>>>((const float4*)h, (const float4*)Wq);
    dim3 g2(ECH, B);
    k_energy<<<g2, 128>>>(pm, aw, cw, Wl, v, mask);
    dim3 g3(TCH, B);
    k_ctx<<<g3, 128>>>((const float4*)mem, out_w, out_ctx);
}

// round 17
// speedup vs baseline: 1.3529x; 1.3529x over previous
#include <cuda_runtime.h>
#include <math.h>

#define B   64
#define T   1000
#define RNN 1024
#define EMB 512
#define ATT 128
#define LOC 32
#define KS  31
#define ECH 10
#define ETILE 100
#define EB  5
#define NPQ 128    // pq blocks (2 per b)
#define TCH 25
#define CTILE 40

__device__ float g_pq[B * ATT];
__device__ float g_energy[B * T];
__device__ float2 g_ms[B * ECH];
__device__ float g_partial[B * TCH * EMB];
__device__ int   g_cnt[B];
__device__ int   g_pq_done[B];   // zero-init; reset by k_ctx each replay

__device__ __forceinline__ float fast_tanh(float x) {
    float y;
    asm("tanh.approx.f32 %0, %1;" : "=f"(y) : "f"(x));
    return y;
}
__device__ __forceinline__ unsigned long long fma2(unsigned long long a,
                                                   unsigned long long b,
                                                   unsigned long long c) {
    unsigned long long d;
    asm("fma.rn.f32x2 %0, %1, %2, %3;" : "=l"(d) : "l"(a), "l"(b), "l"(c));
    return d;
}
__device__ __forceinline__ unsigned long long pack2(float lo, float hi) {
    unsigned long long r;
    asm("mov.b64 %0, {%1, %2};" : "=l"(r) : "f"(lo), "f"(hi));
    return r;
}
__device__ __forceinline__ float sum2(unsigned long long p) {
    float lo, hi;
    asm("mov.b64 {%0, %1}, %2;" : "=f"(lo), "=f"(hi) : "l"(p));
    return lo + hi;
}

// ---------------------------------------------------------------------------
// Kernel A: fused pq + energy.  grid(NPQ + ECH*B), block(128)
//   bid <  NPQ : pq block (b = bid/2, a-half = bid&1), signals g_pq_done[b]
//   bid >= NPQ : energy block (conv first, spin for pq, then projection)
// ---------------------------------------------------------------------------
__global__ void __launch_bounds__(128) k_main(
        const float4* __restrict__ h4, const float4* __restrict__ Wq4,
        const float* __restrict__ pm, const float* __restrict__ aw,
        const float* __restrict__ cw, const float* __restrict__ Wl,
        const float* __restrict__ v,  const unsigned char* __restrict__ mask) {
    int bid = blockIdx.x;
    int tid = threadIdx.x;
    int lane = tid & 31, warp = tid >> 5;

    __shared__ __align__(16) union {
        struct {
            unsigned long long aw2[ETILE + 32];
            unsigned long long cw2[LOC * 33];
        } c;
        float red[ETILE * 4];
        float4 h4s[RNN / 4];
    } u;
    __shared__ __align__(16) float s_loc[ETILE * LOC];
    __shared__ float s_pq[ATT], s_v[ATT];
    __shared__ float s_w4[4];

    // ===================== pq blocks =====================
    if (bid < NPQ) {
        int b = bid >> 1, half = bid & 1;
        for (int i = tid; i < RNN / 4; i += 128)
            u.h4s[i] = h4[b * (RNN / 4) + i];
        __syncthreads();
#pragma unroll
        for (int r = 0; r < 16; r++) {
            int a = half * 64 + warp * 16 + r;
            const float4* w = Wq4 + (size_t)a * (RNN / 4);
            float acc = 0.f;
#pragma unroll
            for (int k = 0; k < 8; k++) {
                float4 wv = w[lane + 32 * k];
                float4 hv = u.h4s[lane + 32 * k];
                acc += wv.x * hv.x + wv.y * hv.y + wv.z * hv.z + wv.w * hv.w;
            }
#pragma unroll
            for (int o = 16; o; o >>= 1) acc += __shfl_down_sync(0xffffffffu, acc, o);
            if (lane == 0) g_pq[b * ATT + a] = acc;
        }
        __threadfence();
        __syncthreads();
        if (tid == 0) atomicAdd(&g_pq_done[b], 1);
        return;
    }

    // ===================== energy blocks =====================
    int eb = bid - NPQ;
    int b = eb / ECH;
    int chunk = eb - b * ECH;
    int t0 = chunk * ETILE;

    for (int j = tid; j < ETILE + 30; j += 128) {
        int t = t0 - 15 + j;
        float c0 = 0.f, c1 = 0.f;
        if (t >= 0 && t < T) {
            c0 = aw[(size_t)b * 2 * T + t];
            c1 = aw[(size_t)(b * 2 + 1) * T + t];
        }
        u.c.aw2[j] = pack2(c0, c1);
    }
    for (int j = tid; j < LOC * KS; j += 128) {
        int c = j / KS, k = j - c * KS;
        u.c.cw2[c * 33 + k] = pack2(cw[c * 62 + k], cw[c * 62 + 31 + k]);
    }
    if (tid < ATT) s_v[tid] = v[tid];
    __syncthreads();

    // conv in 2 passes of 13/12 outputs (k-outer, register-lean) — R10 exact
    {
        int c = lane, wtt = warp;
        {
            unsigned long long acc2[13];
#pragma unroll
            for (int j = 0; j < 13; j++) acc2[j] = 0ull;
            for (int k = 0; k < KS; k++) {
                unsigned long long cwk = u.c.cw2[c * 33 + k];
#pragma unroll
                for (int j = 0; j < 13; j++)
                    acc2[j] = fma2(u.c.aw2[wtt + 4 * j + k], cwk, acc2[j]);
            }
#pragma unroll
            for (int j = 0; j < 13; j++)
                s_loc[(wtt + 4 * j) * LOC + c] = sum2(acc2[j]);
        }
        {
            unsigned long long acc2[12];
#pragma unroll
            for (int j = 0; j < 12; j++) acc2[j] = 0ull;
            for (int k = 0; k < KS; k++) {
                unsigned long long cwk = u.c.cw2[c * 33 + k];
#pragma unroll
                for (int j = 0; j < 12; j++)
                    acc2[j] = fma2(u.c.aw2[wtt + 4 * (13 + j) + k], cwk, acc2[j]);
            }
#pragma unroll
            for (int j = 0; j < 12; j++)
                s_loc[(wtt + 4 * (13 + j)) * LOC + c] = sum2(acc2[j]);
        }
    }

    int a = tid;
    unsigned long long wl2[LOC / 2];
#pragma unroll
    for (int j = 0; j < LOC / 2; j++)
        wl2[j] = pack2(Wl[a * LOC + 2 * j], Wl[a * LOC + 2 * j + 1]);

    // wait for this b's pq (usually already done — hidden under conv)
    if (tid == 0) {
        while (atomicAdd(&g_pq_done[b], 0) < 2) { }
    }
    __syncthreads();   // conv done: u.c dead, u.red live; pq visible
    __threadfence();
    s_pq[tid] = g_pq[b * ATT + tid];
    __syncwarp();
    float pq_a = s_pq[a], v_a = s_v[a];

    const float* pmb = pm + ((size_t)b * T + t0) * ATT + a;
    for (int tt = 0; tt < ETILE; tt += EB) {
        float pmv[EB];
#pragma unroll
        for (int j = 0; j < EB; j++)
            pmv[j] = pmb[(size_t)(tt + j) * ATT];
        float e[EB];
#pragma unroll
        for (int j = 0; j < EB; j++) {
            const ulonglong2* lp = (const ulonglong2*)&s_loc[(tt + j) * LOC];
            unsigned long long a0 = 0ull, a1 = 0ull;
#pragma unroll
            for (int q = 0; q < LOC / 4; q++) {
                ulonglong2 uu = lp[q];
                a0 = fma2(uu.x, wl2[2 * q], a0);
                a1 = fma2(uu.y, wl2[2 * q + 1], a1);
            }
            e[j] = v_a * fast_tanh(pq_a + pmv[j] + sum2(a0) + sum2(a1));
        }
#pragma unroll
        for (int o = 16; o; o >>= 1)
#pragma unroll
            for (int j = 0; j < EB; j++)
                e[j] += __shfl_down_sync(0xffffffffu, e[j], o);
        if (lane == 0)
#pragma unroll
            for (int j = 0; j < EB; j++)
                u.red[(tt + j) * 4 + warp] = e[j];
    }
    __syncthreads();

    float e_t = -INFINITY;
    if (tid < ETILE) {
        e_t = u.red[tid * 4] + u.red[tid * 4 + 1] + u.red[tid * 4 + 2] + u.red[tid * 4 + 3];
        int t = t0 + tid;
        if (mask[b * T + t]) e_t = -INFINITY;
        g_energy[b * T + t] = e_t;
    }
    float m = e_t;
#pragma unroll
    for (int o = 16; o; o >>= 1) m = fmaxf(m, __shfl_xor_sync(0xffffffffu, m, o));
    if (lane == 0) s_w4[warp] = m;
    __syncthreads();
    m = fmaxf(fmaxf(s_w4[0], s_w4[1]), fmaxf(s_w4[2], s_w4[3]));
    float s = (tid < ETILE && m > -INFINITY) ? __expf(e_t - m) : 0.f;
#pragma unroll
    for (int o = 16; o; o >>= 1) s += __shfl_xor_sync(0xffffffffu, s, o);
    __syncthreads();
    if (lane == 0) s_w4[warp] = s;
    __syncthreads();
    if (tid == 0) {
        float2 r; r.x = m; r.y = s_w4[0] + s_w4[1] + s_w4[2] + s_w4[3];
        g_ms[b * ECH + chunk] = r;
    }
}

// ---------------------------------------------------------------------------
// Kernel B: softmax combine + weights + context partials + fused reduce
// grid(TCH, B), block(128). Also resets g_pq_done for next replay.
// ---------------------------------------------------------------------------
__global__ void __launch_bounds__(128) k_ctx(const float4* __restrict__ mem,
                                             float* __restrict__ out_w,
                                             float* __restrict__ out_ctx) {
    int b = blockIdx.y, ch = blockIdx.x, tid = threadIdx.x;
    int t0 = ch * CTILE;
    __shared__ float sw[CTILE];
    __shared__ float2 sms[ECH];
    __shared__ float s_m, s_inv;
    __shared__ int s_last;

    if (ch == 0 && tid == 0) g_pq_done[b] = 0;   // replay-safe reset

    if (tid < ECH) sms[tid] = g_ms[b * ECH + tid];
    __syncthreads();
    if (tid == 0) {
        float m = -INFINITY;
#pragma unroll
        for (int j = 0; j < ECH; j++) m = fmaxf(m, sms[j].x);
        float S = 0.f;
#pragma unroll
        for (int j = 0; j < ECH; j++)
            if (sms[j].x > -INFINITY) S += sms[j].y * __expf(sms[j].x - m);
        s_m = m; s_inv = 1.f / S;
    }
    __syncthreads();
    if (tid < CTILE) {
        float e = g_energy[b * T + t0 + tid];
        float wv = __expf(e - s_m) * s_inv;
        sw[tid] = wv;
        out_w[b * T + t0 + tid] = wv;
    }
    __syncthreads();

    const float4* mp = mem + ((size_t)b * T + t0) * (EMB / 4) + tid;
    float ax = 0.f, ay = 0.f, az = 0.f, aww = 0.f;
#pragma unroll 20
    for (int tt = 0; tt < CTILE; tt++) {
        float4 m = __ldcs(mp + (size_t)tt * (EMB / 4));
        float wv = sw[tt];
        ax += wv * m.x; ay += wv * m.y; az += wv * m.z; aww += wv * m.w;
    }
    float4 r; r.x = ax; r.y = ay; r.z = az; r.w = aww;
    ((float4*)g_partial)[(b * TCH + ch) * (EMB / 4) + tid] = r;

    __threadfence();
    if (tid == 0) {
        int cprev = atomicAdd(&g_cnt[b], 1);
        s_last = (cprev == TCH - 1);
    }
    __syncthreads();
    if (s_last) {
        __threadfence();
        const float4* pp = (const float4*)g_partial + (size_t)b * TCH * (EMB / 4) + tid;
        float4 acc = pp[0];
#pragma unroll
        for (int chh = 1; chh < TCH; chh++) {
            float4 p = pp[(size_t)chh * (EMB / 4)];
            acc.x += p.x; acc.y += p.y; acc.z += p.z; acc.w += p.w;
        }
        ((float4*)out_ctx)[b * (EMB / 4) + tid] = acc;
        if (tid == 0) g_cnt[b] = 0;
    }
}

// ---------------------------------------------------------------------------
extern "C" void kernel_launch(void* const* d_in, const int* in_sizes, int n_in,
                              void* d_out, int out_size) {
    const float* h    = (const float*)d_in[0];
    const float* mem  = (const float*)d_in[1];
    const float* pm   = (const float*)d_in[2];
    const float* aw   = (const float*)d_in[3];
    const unsigned char* mask = (const unsigned char*)d_in[4];
    const float* Wq   = (const float*)d_in[5];
    const float* cw   = (const float*)d_in[6];
    const float* Wl   = (const float*)d_in[7];
    const float* v    = (const float*)d_in[8];

    float* out     = (float*)d_out;
    float* out_ctx = out;
    float* out_w   = out + B * EMB;

    k_main<<<NPQ + ECH * B, 128>>>((const float4*)h, (const float4*)Wq,
                                   pm, aw, cw, Wl, v, mask);
    dim3 g3(TCH, B);
    k_ctx<<<g3, 128>>>((const float4*)mem, out_w, out_ctx);
}